// round 16
// baseline (speedup 1.0000x reference)
#include <cuda_runtime.h>

// AudioLSTM: 2-layer LSTM (26 -> 64 -> 32) over T=1000, B=512, + FC 32->16->10.
// Round 15 = Round 14 design with the launch fixed: both exchange buffers live
// in dynamic smem (52.2KB) and kernel_launch opts in via cudaFuncSetAttribute.
// 4 gate rows (i,f,g,o of one unit) x eighth-K per thread -> one activation
// load feeds 4 rows. Padded sp[.][u][34] exchange, float2 gate-pair stores,
// add2 split-reduction in updaters, producer/consumer BAR B.

#define IN   26
#define H1   64
#define H2   32
#define NB   512
#define TT   1000
#define BPC  4
#define NT   768
#define SPS  34                      // exchange row stride (floats)

#define SP1_FLOATS (BPC * 64 * SPS)              // 8704
#define SP2_FLOATS (BPC * 32 * SPS)              // 4352
#define SMEM_DYN   ((SP1_FLOATS + SP2_FLOATS) * (int)sizeof(float))   // 52224B

typedef unsigned long long ull;

__device__ __forceinline__ ull pack2(float lo, float hi) {
    ull r;
    asm("mov.b64 %0, {%1, %2};" : "=l"(r) : "f"(lo), "f"(hi));
    return r;
}
__device__ __forceinline__ float sum2(ull a) {
    float lo, hi;
    asm("mov.b64 {%0, %1}, %2;" : "=f"(lo), "=f"(hi) : "l"(a));
    return lo + hi;
}
__device__ __forceinline__ float2 unpk(ull a) {
    float lo, hi;
    asm("mov.b64 {%0, %1}, %2;" : "=f"(lo), "=f"(hi) : "l"(a));
    return make_float2(lo, hi);
}
__device__ __forceinline__ ull fma2(ull a, ull b, ull c) {
    ull d;
    asm("fma.rn.f32x2 %0, %1, %2, %3;" : "=l"(d) : "l"(a), "l"(b), "l"(c));
    return d;
}
__device__ __forceinline__ ull add2(ull a, ull b) {
    ull d;
    asm("add.rn.f32x2 %0, %1, %2;" : "=l"(d) : "l"(a), "l"(b));
    return d;
}

#define BAR_A()       asm volatile("bar.sync 0;" ::: "memory")
#define BAR_B_SYNC()  asm volatile("bar.sync 1, %0;" :: "n"(NT) : "memory")
#define BAR_B_ARRV()  asm volatile("bar.arrive 1, %0;" :: "n"(NT) : "memory")

__device__ __forceinline__ float tanha(float x) {
    float y;
    asm("tanh.approx.f32 %0, %1;" : "=f"(y) : "f"(x));
    return y;
}
__device__ __forceinline__ float sigm(float x) {
    return __fmaf_rn(0.5f, tanha(0.5f * x), 0.5f);
}

__global__ void __launch_bounds__(NT, 1)
audiolstm_kernel(const float* __restrict__ x,
                 const float* __restrict__ w_ih1, const float* __restrict__ w_hh1,
                 const float* __restrict__ b_ih1, const float* __restrict__ b_hh1,
                 const float* __restrict__ w_ih2, const float* __restrict__ w_hh2,
                 const float* __restrict__ b_ih2, const float* __restrict__ b_hh2,
                 const float* __restrict__ w_fc1, const float* __restrict__ b_fc1,
                 const float* __restrict__ w_fc2, const float* __restrict__ b_fc2,
                 float* __restrict__ out)
{
    const int b0  = blockIdx.x * BPC;
    const int tid = threadIdx.x;

    extern __shared__ __align__(16) float smem_dyn[];
    float* sp1 = smem_dyn;                         // [BPC][64][SPS]
    float* sp2 = smem_dyn + SP1_FLOATS;            // [BPC][32][SPS]

    __shared__ __align__(16) float sh1[BPC][H1];   // h1(t)
    __shared__ __align__(16) float sh2[BPC][H2];   // h2(t)
    __shared__ __align__(16) float sx[BPC][2][32]; // x dbl buffer, 26..31 = 0
    __shared__ __align__(16) float sb1[4 * H1];
    __shared__ __align__(16) float sb2[4 * H2];
    __shared__ __align__(16) float sf[BPC][16];

    // ---- init (synced by first BAR A) ----
    if (tid < 256) { sh1[tid >> 6][tid & 63] = 0.0f; sb1[tid] = b_ih1[tid] + b_hh1[tid]; }
    if (tid >= 256 && tid < 384) {
        int r = tid - 256;
        sh2[r >> 5][r & 31] = 0.0f;
        sb2[r] = b_ih2[r] + b_hh2[r];
    }
    if (tid >= 384 && tid < 432) {   // zero x pads: floats 26..31, both buffers, 4 batches
        int q = tid - 384;           // 0..47
        int bb = q / 12, rem = q - bb * 12;
        sx[bb][rem / 6][26 + (rem % 6)] = 0.0f;
    }

    if (tid < 512) {
        // ========== Layer 1 gate thread: unit u, split s (eighth-K), 4 rows =====
        const int s = tid >> 6;              // 0..7 (uniform per warp)
        const int u = tid & 63;
        ull wh[4][4], wx[4][2];
        #pragma unroll
        for (int g = 0; g < 4; g++) {
            const int row = g * 64 + u;
            #pragma unroll
            for (int k = 0; k < 4; k++)
                wh[g][k] = pack2(w_hh1[row * H1 + s * 8 + 2 * k],
                                 w_hh1[row * H1 + s * 8 + 2 * k + 1]);
            #pragma unroll
            for (int k = 0; k < 2; k++) {
                int si0 = s * 4 + 2 * k, si1 = si0 + 1;
                float a = (si0 < IN) ? w_ih1[row * IN + si0] : 0.0f;
                float b = (si1 < IN) ? w_ih1[row * IN + si1] : 0.0f;
                wx[g][k] = pack2(a, b);
            }
        }
        const bool upd = (tid < 256);        // warps 0-7
        const int ub = tid >> 6, uj = tid & 63;   // updater: batch ub, unit uj
        float c1 = 0.0f;

        #pragma unroll 1
        for (int t = 0; t <= TT; t++) {
            BAR_A();  // h1(t-1), h2(t-2), sx[t&1] ready
            if (t < TT) {
                const int buf = t & 1;
                #pragma unroll
                for (int bp = 0; bp < 2; bp++) {
                    ull acc[4][2];
                    #pragma unroll
                    for (int g = 0; g < 4; g++) { acc[g][0] = 0ull; acc[g][1] = 0ull; }
                    #pragma unroll
                    for (int j = 0; j < 2; j++) {
                        const int bb = bp * 2 + j;
                        ulonglong2 h0 = ((const ulonglong2*)sh1[bb])[s * 2];
                        ulonglong2 h1v = ((const ulonglong2*)sh1[bb])[s * 2 + 1];
                        ulonglong2 xv = ((const ulonglong2*)sx[bb][buf])[s];
                        #pragma unroll
                        for (int g = 0; g < 4; g++) {
                            acc[g][j] = fma2(h0.x,  wh[g][0], acc[g][j]);
                            acc[g][j] = fma2(h0.y,  wh[g][1], acc[g][j]);
                            acc[g][j] = fma2(h1v.x, wh[g][2], acc[g][j]);
                            acc[g][j] = fma2(h1v.y, wh[g][3], acc[g][j]);
                            acc[g][j] = fma2(xv.x,  wx[g][0], acc[g][j]);
                            acc[g][j] = fma2(xv.y,  wx[g][1], acc[g][j]);
                        }
                    }
                    #pragma unroll
                    for (int j = 0; j < 2; j++) {
                        const int bb = bp * 2 + j;
                        float* p = sp1 + (bb * 64 + u) * SPS + s * 4;
                        *(float2*)p       = make_float2(sum2(acc[0][j]), sum2(acc[1][j]));
                        *(float2*)(p + 2) = make_float2(sum2(acc[2][j]), sum2(acc[3][j]));
                    }
                }
            }
            if (upd) {
                BAR_B_SYNC();   // partials ready
                if (t < TT) {
                    const float* p = sp1 + (ub * 64 + uj) * SPS;
                    ull vif = *(const ull*)p;
                    ull vgo = *(const ull*)(p + 2);
                    #pragma unroll
                    for (int ss = 1; ss < 8; ss++) {
                        vif = add2(vif, *(const ull*)(p + ss * 4));
                        vgo = add2(vgo, *(const ull*)(p + ss * 4 + 2));
                    }
                    float2 vf = unpk(vif), vg = unpk(vgo);
                    float ir = vf.x + sb1[uj];
                    float fr = vf.y + sb1[64 + uj];
                    float gr = vg.x + sb1[128 + uj];
                    float orr = vg.y + sb1[192 + uj];
                    float ig = sigm(ir) * tanha(gr);
                    c1 = __fmaf_rn(sigm(fr), c1, ig);
                    sh1[ub][uj] = sigm(orr) * tanha(c1);
                }
            } else {
                BAR_B_ARRV();   // nothing else to do this phase
            }
        }

        // ---- FC head ----
        BAR_A();  // D1: sh2 holds final h2
        if (tid < BPC * 16) {
            int fb = tid >> 4, fj = tid & 15;
            float acc = b_fc1[fj];
            #pragma unroll
            for (int k = 0; k < H2; k++) acc = __fmaf_rn(w_fc1[fj * H2 + k], sh2[fb][k], acc);
            sf[fb][fj] = fmaxf(acc, 0.0f);
        }
        BAR_A();  // D2
        if (tid < BPC * 10) {
            int fb = tid / 10, fj = tid - fb * 10;
            float acc = b_fc2[fj];
            #pragma unroll
            for (int k = 0; k < 16; k++) acc = __fmaf_rn(w_fc2[fj * 16 + k], sf[fb][k], acc);
            out[(b0 + fb) * 10 + fj] = acc;
        }
    } else {
        // ========== Layer 2 gate thread: unit u2, split s2, 4 rows; lags 1 step ==
        const int tid2 = tid - 512;          // 0..255
        const int s2 = tid2 >> 5;            // 0..7 (uniform per warp)
        const int u2 = tid2 & 31;
        ull wi[4][4], wr[4][2];
        #pragma unroll
        for (int g = 0; g < 4; g++) {
            const int row = g * 32 + u2;
            #pragma unroll
            for (int k = 0; k < 4; k++)
                wi[g][k] = pack2(w_ih2[row * H1 + s2 * 8 + 2 * k],
                                 w_ih2[row * H1 + s2 * 8 + 2 * k + 1]);
            #pragma unroll
            for (int k = 0; k < 2; k++)
                wr[g][k] = pack2(w_hh2[row * H2 + s2 * 4 + 2 * k],
                                 w_hh2[row * H2 + s2 * 4 + 2 * k + 1]);
        }
        const bool upd = (tid2 < 128);       // warps 16-19
        const int ub = tid2 >> 5, uj = tid2 & 31;
        float c2 = 0.0f;

        // x loader role: tid2 in [128, 128+104)
        const bool is_load = (tid2 >= 128 && tid2 < 128 + BPC * IN);
        const int  lq  = tid2 - 128;
        const int  bbx = is_load ? (lq / IN) : 0;
        const int  xi  = lq - bbx * IN;
        const size_t xldbase = (size_t)(b0 + bbx) * (size_t)(IN * TT) + (size_t)xi * TT;
        float xreg = 0.0f;
        if (is_load) {
            sx[bbx][0][xi] = x[xldbase + 0];
            xreg = x[xldbase + 1];
        }

        #pragma unroll 1
        for (int t = 0; t <= TT; t++) {
            BAR_A();
            if (t > 0) {
                #pragma unroll
                for (int bp = 0; bp < 2; bp++) {
                    ull acc[4][2];
                    #pragma unroll
                    for (int g = 0; g < 4; g++) { acc[g][0] = 0ull; acc[g][1] = 0ull; }
                    #pragma unroll
                    for (int j = 0; j < 2; j++) {
                        const int bb = bp * 2 + j;
                        ulonglong2 h0 = ((const ulonglong2*)sh1[bb])[s2 * 2];
                        ulonglong2 h1v = ((const ulonglong2*)sh1[bb])[s2 * 2 + 1];
                        ulonglong2 h2v = ((const ulonglong2*)sh2[bb])[s2];
                        #pragma unroll
                        for (int g = 0; g < 4; g++) {
                            acc[g][j] = fma2(h0.x,  wi[g][0], acc[g][j]);
                            acc[g][j] = fma2(h0.y,  wi[g][1], acc[g][j]);
                            acc[g][j] = fma2(h1v.x, wi[g][2], acc[g][j]);
                            acc[g][j] = fma2(h1v.y, wi[g][3], acc[g][j]);
                            acc[g][j] = fma2(h2v.x, wr[g][0], acc[g][j]);
                            acc[g][j] = fma2(h2v.y, wr[g][1], acc[g][j]);
                        }
                    }
                    #pragma unroll
                    for (int j = 0; j < 2; j++) {
                        const int bb = bp * 2 + j;
                        float* p = sp2 + (bb * 32 + u2) * SPS + s2 * 4;
                        *(float2*)p       = make_float2(sum2(acc[0][j]), sum2(acc[1][j]));
                        *(float2*)(p + 2) = make_float2(sum2(acc[2][j]), sum2(acc[3][j]));
                    }
                }
            }
            if (upd) {
                BAR_B_SYNC();
                if (t > 0) {
                    const float* p = sp2 + (ub * 32 + uj) * SPS;
                    ull vif = *(const ull*)p;
                    ull vgo = *(const ull*)(p + 2);
                    #pragma unroll
                    for (int ss = 1; ss < 8; ss++) {
                        vif = add2(vif, *(const ull*)(p + ss * 4));
                        vgo = add2(vgo, *(const ull*)(p + ss * 4 + 2));
                    }
                    float2 vf = unpk(vif), vg = unpk(vgo);
                    float ir = vf.x + sb2[uj];
                    float fr = vf.y + sb2[32 + uj];
                    float gr = vg.x + sb2[64 + uj];
                    float orr = vg.y + sb2[96 + uj];
                    float ig = sigm(ir) * tanha(gr);
                    c2 = __fmaf_rn(sigm(fr), c2, ig);
                    sh2[ub][uj] = sigm(orr) * tanha(c2);
                }
            } else {
                BAR_B_ARRV();
                if (is_load && (t + 1 < TT)) {
                    sx[bbx][(t + 1) & 1][xi] = xreg;
                    if (t + 2 < TT) xreg = x[xldbase + (t + 2)];
                }
            }
        }
        BAR_A();  // D1
        BAR_A();  // D2
    }
}

extern "C" void kernel_launch(void* const* d_in, const int* in_sizes, int n_in,
                              void* d_out, int out_size)
{
    const float* x     = (const float*)d_in[0];
    const float* w_ih1 = (const float*)d_in[1];
    const float* w_hh1 = (const float*)d_in[2];
    const float* b_ih1 = (const float*)d_in[3];
    const float* b_hh1 = (const float*)d_in[4];
    const float* w_ih2 = (const float*)d_in[5];
    const float* w_hh2 = (const float*)d_in[6];
    const float* b_ih2 = (const float*)d_in[7];
    const float* b_hh2 = (const float*)d_in[8];
    const float* w_fc1 = (const float*)d_in[9];
    const float* b_fc1 = (const float*)d_in[10];
    const float* w_fc2 = (const float*)d_in[11];
    const float* b_fc2 = (const float*)d_in[12];
    float* out = (float*)d_out;

    // Opt in to >48KB dynamic smem. Host-side attribute set: not a sync, not an
    // alloc, enqueues nothing -> legal inside kernel_launch and during capture.
    // Idempotent; called unconditionally (no static guards).
    cudaFuncSetAttribute(audiolstm_kernel,
                         cudaFuncAttributeMaxDynamicSharedMemorySize, SMEM_DYN);

    audiolstm_kernel<<<NB / BPC, NT, SMEM_DYN>>>(x, w_ih1, w_hh1, b_ih1, b_hh1,
                                                 w_ih2, w_hh2, b_ih2, b_hh2,
                                                 w_fc1, b_fc1, w_fc2, b_fc2, out);
}